// round 4
// baseline (speedup 1.0000x reference)
#include <cuda_runtime.h>
#include <cstdint>

#define P_NUM 65536
#define B_NUM 8
#define G_NUM 64
#define NBX 16
#define NBY 16
#define NBINS (NBX * NBY)                 // 256
#define SLOT_CAP (P_NUM + NBINS * 31)     // 73472
#define INVALID_P 0xFFFFFFFFu
#define ENC_MIN(bits) (0x7F800000 - (bits))   // zero-init == +inf identity

// ---------------- persistent device scratch (.bss zero == reset state) ----
__device__ unsigned int       d_bin_count[NBINS];     // reset by k_fixup
__device__ int                d_bb_enc[4][NBINS];     // encMinX,encMinY,maxX,maxY; reset by k_fixup
__device__ unsigned int       d_bin_off[NBINS];
__device__ unsigned int       d_total;                // total padded slots (mult of 32)
__device__ unsigned int       d_binrank[P_NUM];       // bin<<24 | rank
__device__ unsigned short     d_slot_bin[SLOT_CAP];
__device__ unsigned int       d_perm_idx[SLOT_CAP];
__device__ unsigned long long d_cand_mask[B_NUM * NBINS];
__device__ unsigned long long g_best[B_NUM * G_NUM];  // reset by k_fixup

// ---------------- phase A: bin priors (smem-aggregated) ----------------
__global__ __launch_bounds__(256)
void k_bin(const float4* __restrict__ priors)
{
    __shared__ unsigned int s_cnt[NBINS];
    __shared__ int          s_bb[4][NBINS];
    __shared__ unsigned int s_base[NBINS];
    const int tid = threadIdx.x;
    s_cnt[tid] = 0;
    s_bb[0][tid] = 0; s_bb[1][tid] = 0; s_bb[2][tid] = 0; s_bb[3][tid] = 0;
    __syncthreads();

    const int p = blockIdx.x * 256 + tid;
    float4 pr = priors[p];
    float cx = (pr.x + pr.z) * 0.5f;
    float cy = (pr.y + pr.w) * 0.5f;
    int bx = (int)((cx - 0.1f) * (NBX / 0.8f));
    int by = (int)((cy - 0.1f) * (NBY / 0.8f));
    bx = bx < 0 ? 0 : (bx > NBX - 1 ? NBX - 1 : bx);
    by = by < 0 ? 0 : (by > NBY - 1 ? NBY - 1 : by);
    const int bin = by * NBX + bx;
    unsigned int lrank = atomicAdd(&s_cnt[bin], 1u);
    atomicMax(&s_bb[0][bin], ENC_MIN(__float_as_int(pr.x)));
    atomicMax(&s_bb[1][bin], ENC_MIN(__float_as_int(pr.y)));
    atomicMax(&s_bb[2][bin], __float_as_int(pr.z));
    atomicMax(&s_bb[3][bin], __float_as_int(pr.w));
    __syncthreads();

    if (s_cnt[tid] > 0) {
        s_base[tid] = atomicAdd(&d_bin_count[tid], s_cnt[tid]);
        atomicMax(&d_bb_enc[0][tid], s_bb[0][tid]);
        atomicMax(&d_bb_enc[1][tid], s_bb[1][tid]);
        atomicMax(&d_bb_enc[2][tid], s_bb[2][tid]);
        atomicMax(&d_bb_enc[3][tid], s_bb[3][tid]);
    }
    __syncthreads();

    d_binrank[p] = ((unsigned int)bin << 24) | (s_base[bin] + lrank);
}

// ---------------- phase B: block0 = scan + pad; blocks 1..8 = GT masks ----
__global__ __launch_bounds__(256)
void k_scan_cand(const float4* __restrict__ gt_boxes)
{
    const int tid = threadIdx.x;
    if (blockIdx.x == 0) {
        __shared__ unsigned int s[NBINS];
        unsigned int cnt = d_bin_count[tid];
        unsigned int padded = (cnt + 31u) & ~31u;
        s[tid] = padded;
        __syncthreads();
        for (int d = 1; d < NBINS; d <<= 1) {
            unsigned int v = (tid >= d) ? s[tid - d] : 0u;
            __syncthreads();
            s[tid] += v;
            __syncthreads();
        }
        unsigned int off = s[tid] - padded;     // exclusive
        d_bin_off[tid] = off;
        if (tid == NBINS - 1) d_total = s[tid];
        for (unsigned int k = cnt; k < padded; k++)   // pad slots
            d_perm_idx[off + k] = INVALID_P;
    } else {
        __shared__ float4 sg[G_NUM];
        const int b = blockIdx.x - 1;
        if (tid < G_NUM) sg[tid] = gt_boxes[b * G_NUM + tid];
        __syncthreads();
        const int bin = tid;
        float minx0 = __int_as_float(ENC_MIN(d_bb_enc[0][bin]));
        float miny0 = __int_as_float(ENC_MIN(d_bb_enc[1][bin]));
        float maxx1 = __int_as_float(d_bb_enc[2][bin]);
        float maxy1 = __int_as_float(d_bb_enc[3][bin]);
        unsigned long long mask = 0ull;
        for (int g = 0; g < G_NUM; g++) {
            float4 gb = sg[g];
            // exact conservative reject: skipped pairs have intersection == 0
            bool keep = (gb.z > minx0) & (gb.x < maxx1) &
                        (gb.w > miny0) & (gb.y < maxy1);
            if (keep) mask |= 1ull << g;
        }
        d_cand_mask[(b << 8) | bin] = mask;
    }
}

// ---------------- phase C: scatter permutation (small scattered writes) --
__global__ __launch_bounds__(256)
void k_scatter(void)
{
    const int p = blockIdx.x * 256 + threadIdx.x;
    unsigned int br = d_binrank[p];
    unsigned int bin = br >> 24;
    unsigned int slot = d_bin_off[bin] + (br & 0xFFFFFFu);
    d_perm_idx[slot] = (unsigned int)p;
    d_slot_bin[slot] = (unsigned short)bin;
}

// ---------------- phase D: main matching ----------------
__global__ __launch_bounds__(256)
void k_match(const float4* __restrict__ priors,
             const float4* __restrict__ gt_boxes,
             const int*    __restrict__ gt_labels,
             float* __restrict__ out_loc,
             float* __restrict__ out_conf)
{
    __shared__ float4 s_box[G_NUM];
    __shared__ float  s_area[G_NUM];
    __shared__ int    s_lab[G_NUM];
    __shared__ unsigned long long s_best[G_NUM];

    const int b    = blockIdx.y;
    const int tid  = threadIdx.x;
    const int lane = tid & 31;

    if (tid < G_NUM) {
        float4 g4 = gt_boxes[b * G_NUM + tid];
        s_box[tid]  = g4;
        s_area[tid] = (g4.z - g4.x) * (g4.w - g4.y);
        s_lab[tid]  = gt_labels[b * G_NUM + tid];
        s_best[tid] = 0ull;
    }
    __syncthreads();

    const unsigned int slot = blockIdx.x * 256 + tid;
    if (slot < d_total) {                               // warp-uniform (total % 32 == 0)
        const unsigned int p = d_perm_idx[slot];
        const int bin = __shfl_sync(0xffffffffu, (int)d_slot_bin[slot], 0);

        float4 pr;
        if (p != INVALID_P) pr = priors[p];
        else                pr = make_float4(-10.0f, -10.0f, -9.9f, -9.9f); // IoU == 0
        const float pa = (pr.z - pr.x) * (pr.w - pr.y);

        float best_iou = 0.0f;        // all-zero column -> g=0 (jnp.argmax)
        int   best_g   = 0;

        unsigned long long m = d_cand_mask[(b << 8) | bin];
        while (m) {
            const int g = __ffsll((long long)m) - 1;    // ascending g
            m &= m - 1;
            const float4 gb = s_box[g];
            const float  ga = s_area[g];
            float ltx = fmaxf(pr.x, gb.x);
            float lty = fmaxf(pr.y, gb.y);
            float rbx = fminf(pr.z, gb.z);
            float rby = fminf(pr.w, gb.w);
            float wx  = fmaxf(rbx - ltx, 0.0f);
            float wy  = fmaxf(rby - lty, 0.0f);
            float inter = wx * wy;
            float uni   = (pa + ga) - inter;
            float iou   = inter / uni;
            if (iou > best_iou) { best_iou = iou; best_g = g; }  // first max wins

            unsigned int ub = __float_as_uint(iou);              // iou >= 0: monotone bits
            unsigned int wb = __reduce_max_sync(0xffffffffu, ub);
            unsigned int candp = (ub == wb) ? p : INVALID_P;     // pad lanes excluded
            unsigned int mp = __reduce_min_sync(0xffffffffu, candp);
            if (lane == 0 && wb != 0u) {
                unsigned long long key =
                    ((unsigned long long)wb << 32) | (unsigned long long)(~mp);
                atomicMax(&s_best[g], key);
            }
        }

        if (p != INVALID_P) {
            const float4 mb = s_box[best_g];
            const int    cv = (best_iou < 0.5f) ? 0 : (s_lab[best_g] + 1);
            float pcx = (pr.x + pr.z) * 0.5f;
            float pcy = (pr.y + pr.w) * 0.5f;
            float pw  = pr.z - pr.x;
            float ph  = pr.w - pr.y;
            float gcx = (mb.x + mb.z) * 0.5f;
            float gcy = (mb.y + mb.w) * 0.5f;
            float gw  = mb.z - mb.x;
            float gh  = mb.w - mb.y;
            float4 loc;
            loc.x = (gcx - pcx) / (0.1f * pw);
            loc.y = (gcy - pcy) / (0.1f * ph);
            loc.z = logf(gw / pw) / 0.2f;
            loc.w = logf(gh / ph) / 0.2f;
            reinterpret_cast<float4*>(out_loc)[(size_t)b * P_NUM + p] = loc;
            if (out_conf) out_conf[(size_t)b * P_NUM + p] = (float)cv;
        }
    }

    __syncthreads();
    if (tid < G_NUM) {
        unsigned long long v = s_best[tid];
        if (v) atomicMax(&g_best[(b << 6) + tid], v);
    }
}

// ---------------- phase E: forced-prior fixup + reset for next call ------
// Replicates scatter semantics: for duplicate priors, the LAST g wins.
__global__ void k_fixup(const float4* __restrict__ priors,
                        const float4* __restrict__ gt_boxes,
                        const int*    __restrict__ gt_labels,
                        float* __restrict__ out_loc,
                        float* __restrict__ out_conf)
{
    __shared__ unsigned int sp[B_NUM * G_NUM];
    const int tid = threadIdx.x;                 // 512 threads = (b,g)
    const unsigned long long key = g_best[tid];
    g_best[tid] = 0ull;                          // restore .bss state
    if (tid < NBINS) {                           // restore bin scratch
        d_bin_count[tid] = 0;
        d_bb_enc[0][tid] = 0; d_bb_enc[1][tid] = 0;
        d_bb_enc[2][tid] = 0; d_bb_enc[3][tid] = 0;
    }
    const unsigned int p = ~((unsigned int)(key & 0xFFFFFFFFull));
    sp[tid] = p;
    __syncthreads();

    if (key == 0ull) return;                     // GT overlapped nothing

    const int b = tid >> 6;
    const int g = tid & 63;
    for (int g2 = g + 1; g2 < G_NUM; g2++)
        if (sp[(b << 6) + g2] == p) return;      // later g claims same prior

    const float4 m  = gt_boxes[b * G_NUM + g];
    const float4 pb = priors[p];
    float pcx = (pb.x + pb.z) * 0.5f;
    float pcy = (pb.y + pb.w) * 0.5f;
    float pw  = pb.z - pb.x;
    float ph  = pb.w - pb.y;
    float gcx = (m.x + m.z) * 0.5f;
    float gcy = (m.y + m.w) * 0.5f;
    float gw  = m.z - m.x;
    float gh  = m.w - m.y;
    float4 loc;
    loc.x = (gcx - pcx) / (0.1f * pw);
    loc.y = (gcy - pcy) / (0.1f * ph);
    loc.z = logf(gw / pw) / 0.2f;
    loc.w = logf(gh / ph) / 0.2f;
    reinterpret_cast<float4*>(out_loc)[(size_t)b * P_NUM + p] = loc;
    if (out_conf) out_conf[(size_t)b * P_NUM + p] = (float)(gt_labels[b * G_NUM + g] + 1);
}

extern "C" void kernel_launch(void* const* d_in, const int* in_sizes, int n_in,
                              void* d_out, int out_size)
{
    const float4* priors    = (const float4*)d_in[0];   // [P,4] f32
    const float4* gt_boxes  = (const float4*)d_in[1];   // [B,G,4] f32
    const int*    gt_labels = (const int*)d_in[2];      // [B,G] i32

    float* out = (float*)d_out;
    float* out_loc  = out;                                           // [B,P,4]
    float* out_conf = (out_size >= B_NUM * P_NUM * 5)
                        ? out + (size_t)B_NUM * P_NUM * 4 : nullptr; // [B,P]

    k_bin      <<<P_NUM / 256, 256>>>(priors);
    k_scan_cand<<<1 + B_NUM, 256>>>(gt_boxes);
    k_scatter  <<<P_NUM / 256, 256>>>();
    dim3 grid(SLOT_CAP / 256, B_NUM);                                // (287, 8)
    k_match    <<<grid, 256>>>(priors, gt_boxes, gt_labels, out_loc, out_conf);
    k_fixup    <<<1, B_NUM * G_NUM>>>(priors, gt_boxes, gt_labels, out_loc, out_conf);
}

// round 5
// speedup vs baseline: 1.1712x; 1.1712x over previous
#include <cuda_runtime.h>
#include <cstdint>

#define P_NUM 65536
#define B_NUM 8
#define G_NUM 64
#define NBX 16
#define NBY 16
#define NBINS 1024                        // 4 size classes x 256 center bins
#define P_BITS 17
#define P_MASK 0x1FFFFu
#define INVALID_P 0xFFFFFFFFu
#define ENC_MIN(bits) (0x7F800000 - (bits))   // zero-init == +inf identity

// ---------------- persistent device scratch (.bss zero == reset state) ----
__device__ unsigned int       d_bin_count[NBINS];     // reset by k_fixup
__device__ int                d_bb_enc[4][NBINS];     // encMinX,encMinY,maxX,maxY; reset by k_fixup
__device__ unsigned int       d_bin_off[NBINS];
__device__ unsigned int       d_binrank[P_NUM];       // bin<<20 | rank
__device__ unsigned int       d_perm[P_NUM];          // bin<<17 | p
__device__ unsigned long long d_cand_mask[B_NUM * NBINS];
__device__ unsigned long long g_best[B_NUM * G_NUM];  // reset by k_fixup

// ---------------- phase A: bin priors (smem-aggregated) ----------------
__global__ __launch_bounds__(512)
void k_bin(const float4* __restrict__ priors)
{
    __shared__ unsigned int s_cnt[NBINS];
    __shared__ int          s_bb[4][NBINS];
    __shared__ unsigned int s_base[NBINS];
    const int tid = threadIdx.x;
    for (int i = tid; i < NBINS; i += 512) {
        s_cnt[i] = 0;
        s_bb[0][i] = 0; s_bb[1][i] = 0; s_bb[2][i] = 0; s_bb[3][i] = 0;
    }
    __syncthreads();

    const int p = blockIdx.x * 512 + tid;
    float4 pr = priors[p];
    float cx = (pr.x + pr.z) * 0.5f;
    float cy = (pr.y + pr.w) * 0.5f;
    int bx = (int)((cx - 0.1f) * (NBX / 0.8f));
    int by = (int)((cy - 0.1f) * (NBY / 0.8f));
    bx = bx < 0 ? 0 : (bx > NBX - 1 ? NBX - 1 : bx);
    by = by < 0 ? 0 : (by > NBY - 1 ? NBY - 1 : by);
    int cls = ((pr.z - pr.x) >= 0.12f ? 1 : 0) | ((pr.w - pr.y) >= 0.12f ? 2 : 0);
    const int bin = (cls << 8) | (by * NBX + bx);
    unsigned int lrank = atomicAdd(&s_cnt[bin], 1u);
    atomicMax(&s_bb[0][bin], ENC_MIN(__float_as_int(pr.x)));
    atomicMax(&s_bb[1][bin], ENC_MIN(__float_as_int(pr.y)));
    atomicMax(&s_bb[2][bin], __float_as_int(pr.z));
    atomicMax(&s_bb[3][bin], __float_as_int(pr.w));
    __syncthreads();

    for (int i = tid; i < NBINS; i += 512) {
        if (s_cnt[i] > 0) {
            s_base[i] = atomicAdd(&d_bin_count[i], s_cnt[i]);
            atomicMax(&d_bb_enc[0][i], s_bb[0][i]);
            atomicMax(&d_bb_enc[1][i], s_bb[1][i]);
            atomicMax(&d_bb_enc[2][i], s_bb[2][i]);
            atomicMax(&d_bb_enc[3][i], s_bb[3][i]);
        }
    }
    __syncthreads();

    d_binrank[p] = ((unsigned int)bin << 20) | (s_base[bin] + lrank);
}

// ---------------- phase B: block0 = scan; blocks 1..8 = GT masks ----------
__global__ __launch_bounds__(1024)
void k_scan_cand(const float4* __restrict__ gt_boxes)
{
    const int tid = threadIdx.x;
    if (blockIdx.x == 0) {
        __shared__ unsigned int s[NBINS];
        unsigned int cnt = d_bin_count[tid];
        s[tid] = cnt;
        __syncthreads();
        for (int d = 1; d < NBINS; d <<= 1) {
            unsigned int v = (tid >= d) ? s[tid - d] : 0u;
            __syncthreads();
            s[tid] += v;
            __syncthreads();
        }
        d_bin_off[tid] = s[tid] - cnt;    // exclusive scan, no padding
    } else {
        __shared__ float4 sg[G_NUM];
        const int b = blockIdx.x - 1;
        if (tid < G_NUM) sg[tid] = gt_boxes[b * G_NUM + tid];
        __syncthreads();
        const int bin = tid;
        float minx0 = __int_as_float(ENC_MIN(d_bb_enc[0][bin]));
        float miny0 = __int_as_float(ENC_MIN(d_bb_enc[1][bin]));
        float maxx1 = __int_as_float(d_bb_enc[2][bin]);
        float maxy1 = __int_as_float(d_bb_enc[3][bin]);
        unsigned long long mask = 0ull;
        for (int g = 0; g < G_NUM; g++) {
            float4 gb = sg[g];
            // exact conservative reject: skipped pairs have intersection == 0
            bool keep = (gb.z > minx0) & (gb.x < maxx1) &
                        (gb.w > miny0) & (gb.y < maxy1);
            if (keep) mask |= 1ull << g;
        }
        d_cand_mask[(b << 10) | bin] = mask;
    }
}

// ---------------- phase C: scatter permutation (one 4B write) -------------
__global__ __launch_bounds__(256)
void k_scatter(void)
{
    const int p = blockIdx.x * 256 + threadIdx.x;
    unsigned int br   = d_binrank[p];
    unsigned int bin  = br >> 20;
    unsigned int slot = d_bin_off[bin] + (br & 0xFFFFFu);
    d_perm[slot] = (bin << P_BITS) | (unsigned int)p;
}

// ---------------- phase D: main matching ----------------
__global__ __launch_bounds__(256)
void k_match(const float4* __restrict__ priors,
             const float4* __restrict__ gt_boxes,
             const int*    __restrict__ gt_labels,
             float* __restrict__ out_loc,
             float* __restrict__ out_conf)
{
    __shared__ float4 s_box[G_NUM];
    __shared__ float  s_area[G_NUM];
    __shared__ int    s_lab[G_NUM];
    __shared__ unsigned long long s_best[G_NUM];

    const int b   = blockIdx.y;
    const int tid = threadIdx.x;

    if (tid < G_NUM) {
        float4 g4 = gt_boxes[b * G_NUM + tid];
        s_box[tid]  = g4;
        s_area[tid] = (g4.z - g4.x) * (g4.w - g4.y);
        s_lab[tid]  = gt_labels[b * G_NUM + tid];
        s_best[tid] = 0ull;
    }
    __syncthreads();

    const unsigned int entry = d_perm[blockIdx.x * 256 + tid];
    const unsigned int p   = entry & P_MASK;
    const unsigned int bin = entry >> P_BITS;

    // union mask over the (at most 2) bins this warp straddles —
    // conservative => extra evaluated pairs have IoU exactly 0 (harmless)
    const unsigned int bin_lo = __shfl_sync(0xffffffffu, bin, 0);
    const unsigned int bin_hi = __shfl_sync(0xffffffffu, bin, 31);
    unsigned long long m = d_cand_mask[(b << 10) | bin_lo];
    if (bin_hi != bin_lo) m |= d_cand_mask[(b << 10) | bin_hi];

    const float4 pr = priors[p];
    const float  pa = (pr.z - pr.x) * (pr.w - pr.y);

    float best_iou = 0.0f;        // all-zero column -> g=0 (jnp.argmax)
    int   best_g   = 0;

    while (m) {
        const int g = __ffsll((long long)m) - 1;    // ascending g
        m &= m - 1;
        const float4 gb = s_box[g];
        const float  ga = s_area[g];
        float ltx = fmaxf(pr.x, gb.x);
        float lty = fmaxf(pr.y, gb.y);
        float rbx = fminf(pr.z, gb.z);
        float rby = fminf(pr.w, gb.w);
        float wx  = fmaxf(rbx - ltx, 0.0f);
        float wy  = fmaxf(rby - lty, 0.0f);
        float inter = wx * wy;
        float uni   = (pa + ga) - inter;
        float iou   = inter / uni;
        if (iou > best_iou) { best_iou = iou; best_g = g; }   // first max wins

        // per-GT column argmax: winners race via atomicMax; ~p makes
        // the max pick the smallest p (first-occurrence tie-break)
        unsigned int ub = __float_as_uint(iou);               // iou >= 0: monotone
        unsigned int wb = __reduce_max_sync(0xffffffffu, ub);
        if (ub == wb && wb != 0u) {
            unsigned long long key =
                ((unsigned long long)wb << 32) | (unsigned long long)(~p);
            atomicMax(&s_best[g], key);
        }
    }

    {
        const float4 mb = s_box[best_g];
        const int    cv = (best_iou < 0.5f) ? 0 : (s_lab[best_g] + 1);
        float pcx = (pr.x + pr.z) * 0.5f;
        float pcy = (pr.y + pr.w) * 0.5f;
        float pw  = pr.z - pr.x;
        float ph  = pr.w - pr.y;
        float gcx = (mb.x + mb.z) * 0.5f;
        float gcy = (mb.y + mb.w) * 0.5f;
        float gw  = mb.z - mb.x;
        float gh  = mb.w - mb.y;
        float4 loc;
        loc.x = (gcx - pcx) / (0.1f * pw);
        loc.y = (gcy - pcy) / (0.1f * ph);
        loc.z = logf(gw / pw) / 0.2f;
        loc.w = logf(gh / ph) / 0.2f;
        reinterpret_cast<float4*>(out_loc)[(size_t)b * P_NUM + p] = loc;
        if (out_conf) out_conf[(size_t)b * P_NUM + p] = (float)cv;
    }

    __syncthreads();
    if (tid < G_NUM) {
        unsigned long long v = s_best[tid];
        if (v) atomicMax(&g_best[(b << 6) + tid], v);
    }
}

// ---------------- phase E: forced-prior fixup + reset for next call ------
// Replicates scatter semantics: for duplicate priors, the LAST g wins.
__global__ void k_fixup(const float4* __restrict__ priors,
                        const float4* __restrict__ gt_boxes,
                        const int*    __restrict__ gt_labels,
                        float* __restrict__ out_loc,
                        float* __restrict__ out_conf)
{
    __shared__ unsigned int sp[B_NUM * G_NUM];
    const int tid = threadIdx.x;                 // 512 threads = (b,g)
    const unsigned long long key = g_best[tid];
    g_best[tid] = 0ull;                          // restore .bss state
    for (int i = tid; i < NBINS; i += 512) {     // restore bin scratch
        d_bin_count[i] = 0;
        d_bb_enc[0][i] = 0; d_bb_enc[1][i] = 0;
        d_bb_enc[2][i] = 0; d_bb_enc[3][i] = 0;
    }
    const unsigned int p = ~((unsigned int)(key & 0xFFFFFFFFull));
    sp[tid] = p;
    __syncthreads();

    if (key == 0ull) return;                     // GT overlapped nothing

    const int b = tid >> 6;
    const int g = tid & 63;
    for (int g2 = g + 1; g2 < G_NUM; g2++)
        if (sp[(b << 6) + g2] == p) return;      // later g claims same prior

    const float4 m  = gt_boxes[b * G_NUM + g];
    const float4 pb = priors[p];
    float pcx = (pb.x + pb.z) * 0.5f;
    float pcy = (pb.y + pb.w) * 0.5f;
    float pw  = pb.z - pb.x;
    float ph  = pb.w - pb.y;
    float gcx = (m.x + m.z) * 0.5f;
    float gcy = (m.y + m.w) * 0.5f;
    float gw  = m.z - m.x;
    float gh  = m.w - m.y;
    float4 loc;
    loc.x = (gcx - pcx) / (0.1f * pw);
    loc.y = (gcy - pcy) / (0.1f * ph);
    loc.z = logf(gw / pw) / 0.2f;
    loc.w = logf(gh / ph) / 0.2f;
    reinterpret_cast<float4*>(out_loc)[(size_t)b * P_NUM + p] = loc;
    if (out_conf) out_conf[(size_t)b * P_NUM + p] = (float)(gt_labels[b * G_NUM + g] + 1);
}

extern "C" void kernel_launch(void* const* d_in, const int* in_sizes, int n_in,
                              void* d_out, int out_size)
{
    const float4* priors    = (const float4*)d_in[0];   // [P,4] f32
    const float4* gt_boxes  = (const float4*)d_in[1];   // [B,G,4] f32
    const int*    gt_labels = (const int*)d_in[2];      // [B,G] i32

    float* out = (float*)d_out;
    float* out_loc  = out;                                           // [B,P,4]
    float* out_conf = (out_size >= B_NUM * P_NUM * 5)
                        ? out + (size_t)B_NUM * P_NUM * 4 : nullptr; // [B,P]

    k_bin      <<<P_NUM / 512, 512>>>(priors);
    k_scan_cand<<<1 + B_NUM, 1024>>>(gt_boxes);
    k_scatter  <<<P_NUM / 256, 256>>>();
    dim3 grid(P_NUM / 256, B_NUM);                                   // (256, 8)
    k_match    <<<grid, 256>>>(priors, gt_boxes, gt_labels, out_loc, out_conf);
    k_fixup    <<<1, B_NUM * G_NUM>>>(priors, gt_boxes, gt_labels, out_loc, out_conf);
}